// round 1
// baseline (speedup 1.0000x reference)
#include <cuda_runtime.h>
#include <cstddef>

// Problem constants (match reference)
#define NMAX 100000
#define EMAX 1600000
#define K_DIM 128

// ---- Scratch (device globals; no allocations allowed) ----
__device__ int   g_deg[NMAX];
__device__ int   g_rowptr[NMAX + 1];
__device__ int   g_fill[NMAX];
__device__ int   g_col[EMAX];
__device__ float g_xl[(size_t)NMAX * 128];   // aggregated-path transform
__device__ float g_xr[(size_t)NMAX * 128];   // self-path transform (+bias)
__device__ float g_h[(size_t)NMAX * 128];    // layer-0 output
__device__ float g_h2[(size_t)NMAX * 128];   // layer-1 output

// ============================================================
// CSR build (counting sort by dst), rebuilt every launch
// ============================================================
__global__ void zero_deg_k(int n) {
    int i = blockIdx.x * blockDim.x + threadIdx.x;
    if (i < n) g_deg[i] = 0;
}

__global__ void hist_k(const int* __restrict__ dst, int e) {
    int i = blockIdx.x * blockDim.x + threadIdx.x;
    if (i < e) atomicAdd(&g_deg[dst[i]], 1);
}

__global__ __launch_bounds__(1024) void scan_k(int n) {
    __shared__ int part[1024];
    int tid = threadIdx.x;
    int chunk = (n + 1023) >> 10;
    int beg = tid * chunk;
    int end = min(beg + chunk, n);
    int s = 0;
    for (int i = beg; i < end; i++) s += g_deg[i];
    part[tid] = s;
    __syncthreads();
    // Hillis-Steele inclusive scan
    for (int off = 1; off < 1024; off <<= 1) {
        int v = (tid >= off) ? part[tid - off] : 0;
        __syncthreads();
        part[tid] += v;
        __syncthreads();
    }
    int base = part[tid] - s;  // exclusive prefix
    for (int i = beg; i < end; i++) {
        g_rowptr[i] = base;
        g_fill[i]   = base;
        base += g_deg[i];
    }
    if (tid == 1023) g_rowptr[n] = part[1023];
}

__global__ void scatter_k(const int* __restrict__ src, const int* __restrict__ dst, int e) {
    int i = blockIdx.x * blockDim.x + threadIdx.x;
    if (i < e) {
        int p = atomicAdd(&g_fill[dst[i]], 1);
        g_col[p] = src[i];
    }
}

// ============================================================
// Fused dual GEMM:  Cl = A @ Wl ;  Cr = A @ Wr + bias
// A: [n,128] row-major, W: [128,DOUT] row-major.
// blockIdx.y selects which matmul; BM=64 rows per block.
// ============================================================
template <int DOUT>
__global__ __launch_bounds__(256) void gemm_fused(
    const float* __restrict__ A,
    const float* __restrict__ Wl, const float* __restrict__ Wr,
    const float* __restrict__ bias,
    float* __restrict__ Cl, float* __restrict__ Cr, int n)
{
    constexpr int BM = 64, BK = 16;
    constexpr int TM = 4, TN = DOUT / 16;

    __shared__ float As[BK][BM];     // k-major
    __shared__ float Bs[BK][DOUT];   // k-major

    const float* W = blockIdx.y ? Wr : Wl;
    float*       C = blockIdx.y ? Cr : Cl;
    const bool use_bias = (blockIdx.y == 1);

    const int row0 = blockIdx.x * BM;
    const int tid  = threadIdx.x;
    const int tx   = tid & 15;   // col group
    const int ty   = tid >> 4;   // row group

    float acc[TM][TN];
#pragma unroll
    for (int i = 0; i < TM; i++)
#pragma unroll
        for (int j = 0; j < TN; j++) acc[i][j] = 0.f;

    const int ar  = tid >> 2;        // 0..63 (row within tile)
    const int ak  = (tid & 3) * 4;   // 0,4,8,12 (k offset)
    const int agr = row0 + ar;
    const bool avalid = (agr < n);

    for (int k0 = 0; k0 < K_DIM; k0 += BK) {
        float4 av = make_float4(0.f, 0.f, 0.f, 0.f);
        if (avalid)
            av = *(const float4*)(A + (size_t)agr * K_DIM + k0 + ak);
        As[ak + 0][ar] = av.x;
        As[ak + 1][ar] = av.y;
        As[ak + 2][ar] = av.z;
        As[ak + 3][ar] = av.w;

#pragma unroll
        for (int v = 0; v < (BK * DOUT) / 1024; v++) {
            int idx = (tid + v * 256) * 4;
            int kk = idx / DOUT;
            int c  = idx % DOUT;
            *(float4*)&Bs[kk][c] = *(const float4*)(W + (size_t)(k0 + kk) * DOUT + c);
        }
        __syncthreads();

#pragma unroll
        for (int kk = 0; kk < BK; kk++) {
            float a[TM], b[TN];
#pragma unroll
            for (int i = 0; i < TM; i++) a[i] = As[kk][ty * TM + i];
#pragma unroll
            for (int j = 0; j < TN; j++) b[j] = Bs[kk][tx * TN + j];
#pragma unroll
            for (int i = 0; i < TM; i++)
#pragma unroll
                for (int j = 0; j < TN; j++)
                    acc[i][j] = fmaf(a[i], b[j], acc[i][j]);
        }
        __syncthreads();
    }

    float bv[TN];
#pragma unroll
    for (int j = 0; j < TN; j++) bv[j] = use_bias ? bias[tx * TN + j] : 0.f;

#pragma unroll
    for (int i = 0; i < TM; i++) {
        int gr = row0 + ty * TM + i;
        if (gr < n) {
#pragma unroll
            for (int j = 0; j < TN; j += 4) {
                float4 o;
                o.x = acc[i][j + 0] + bv[j + 0];
                o.y = acc[i][j + 1] + bv[j + 1];
                o.z = acc[i][j + 2] + bv[j + 2];
                o.w = acc[i][j + 3] + bv[j + 3];
                *(float4*)(C + (size_t)gr * DOUT + tx * TN + j) = o;
            }
        }
    }
}

// ============================================================
// Aggregation + epilogue: out[n] = relu?( mean_{s in N(n)} xl[s] + xr[n] )
// One warp per destination node; register accumulation (no atomics).
// ============================================================
template <int DOUT, bool RELU>
__global__ __launch_bounds__(256) void agg_ep(
    const float* __restrict__ xl, const float* __restrict__ xr,
    float* __restrict__ out, int n)
{
    int gw   = (blockIdx.x * blockDim.x + threadIdx.x) >> 5;
    int lane = threadIdx.x & 31;
    if (gw >= n) return;

    int beg = g_rowptr[gw];
    int end = g_rowptr[gw + 1];
    float inv = 1.f / fmaxf((float)(end - beg), 1.f);

    if (DOUT == 128) {
        const float4* X = (const float4*)xl;
        float4 a0 = {0,0,0,0}, a1 = {0,0,0,0}, a2 = {0,0,0,0}, a3 = {0,0,0,0};
        int e = beg;
        for (; e + 3 < end; e += 4) {
            int s0 = g_col[e], s1 = g_col[e + 1], s2 = g_col[e + 2], s3 = g_col[e + 3];
            float4 v0 = X[s0 * 32 + lane];
            float4 v1 = X[s1 * 32 + lane];
            float4 v2 = X[s2 * 32 + lane];
            float4 v3 = X[s3 * 32 + lane];
            a0.x += v0.x; a0.y += v0.y; a0.z += v0.z; a0.w += v0.w;
            a1.x += v1.x; a1.y += v1.y; a1.z += v1.z; a1.w += v1.w;
            a2.x += v2.x; a2.y += v2.y; a2.z += v2.z; a2.w += v2.w;
            a3.x += v3.x; a3.y += v3.y; a3.z += v3.z; a3.w += v3.w;
        }
        for (; e < end; e++) {
            int s = g_col[e];
            float4 v = X[s * 32 + lane];
            a0.x += v.x; a0.y += v.y; a0.z += v.z; a0.w += v.w;
        }
        float4 r = ((const float4*)xr)[gw * 32 + lane];
        float4 o;
        o.x = (a0.x + a1.x + a2.x + a3.x) * inv + r.x;
        o.y = (a0.y + a1.y + a2.y + a3.y) * inv + r.y;
        o.z = (a0.z + a1.z + a2.z + a3.z) * inv + r.z;
        o.w = (a0.w + a1.w + a2.w + a3.w) * inv + r.w;
        if (RELU) {
            o.x = fmaxf(o.x, 0.f); o.y = fmaxf(o.y, 0.f);
            o.z = fmaxf(o.z, 0.f); o.w = fmaxf(o.w, 0.f);
        }
        ((float4*)out)[gw * 32 + lane] = o;
    } else {  // DOUT == 64
        const float2* X = (const float2*)xl;
        float2 a0 = {0,0}, a1 = {0,0}, a2 = {0,0}, a3 = {0,0};
        int e = beg;
        for (; e + 3 < end; e += 4) {
            int s0 = g_col[e], s1 = g_col[e + 1], s2 = g_col[e + 2], s3 = g_col[e + 3];
            float2 v0 = X[s0 * 32 + lane];
            float2 v1 = X[s1 * 32 + lane];
            float2 v2 = X[s2 * 32 + lane];
            float2 v3 = X[s3 * 32 + lane];
            a0.x += v0.x; a0.y += v0.y;
            a1.x += v1.x; a1.y += v1.y;
            a2.x += v2.x; a2.y += v2.y;
            a3.x += v3.x; a3.y += v3.y;
        }
        for (; e < end; e++) {
            int s = g_col[e];
            float2 v = X[s * 32 + lane];
            a0.x += v.x; a0.y += v.y;
        }
        float2 r = ((const float2*)xr)[gw * 32 + lane];
        float2 o;
        o.x = (a0.x + a1.x + a2.x + a3.x) * inv + r.x;
        o.y = (a0.y + a1.y + a2.y + a3.y) * inv + r.y;
        if (RELU) { o.x = fmaxf(o.x, 0.f); o.y = fmaxf(o.y, 0.f); }
        ((float2*)out)[gw * 32 + lane] = o;
    }
}

// ============================================================
// Launch
// ============================================================
extern "C" void kernel_launch(void* const* d_in, const int* in_sizes, int n_in,
                              void* d_out, int out_size)
{
    const float* x   = (const float*)d_in[0];
    const int*   ei  = (const int*)d_in[1];
    const float* Wl0 = (const float*)d_in[2];
    const float* Wr0 = (const float*)d_in[3];
    const float* b0  = (const float*)d_in[4];
    const float* Wl1 = (const float*)d_in[5];
    const float* Wr1 = (const float*)d_in[6];
    const float* b1  = (const float*)d_in[7];
    const float* Wl2 = (const float*)d_in[8];
    const float* Wr2 = (const float*)d_in[9];
    const float* b2  = (const float*)d_in[10];

    const int n = in_sizes[0] / 128;
    const int e = in_sizes[1] / 2;
    const int* src = ei;
    const int* dst = ei + e;

    void *pxl, *pxr, *ph, *ph2;
    cudaGetSymbolAddress(&pxl, g_xl);
    cudaGetSymbolAddress(&pxr, g_xr);
    cudaGetSymbolAddress(&ph,  g_h);
    cudaGetSymbolAddress(&ph2, g_h2);
    float* f_xl = (float*)pxl;
    float* f_xr = (float*)pxr;
    float* f_h  = (float*)ph;
    float* f_h2 = (float*)ph2;

    // CSR build (per-launch; deterministic up to fp32 summation order)
    zero_deg_k<<<(n + 255) / 256, 256>>>(n);
    hist_k<<<(e + 255) / 256, 256>>>(dst, e);
    scan_k<<<1, 1024>>>(n);
    scatter_k<<<(e + 255) / 256, 256>>>(src, dst, e);

    dim3 gg((n + 63) / 64, 2);
    int agg_blocks = (n + 7) / 8;  // 8 warps/block, one warp per node

    // Layer 0: h = relu(mean_agg(x@Wl0) + x@Wr0 + b0)
    gemm_fused<128><<<gg, 256>>>(x, Wl0, Wr0, b0, f_xl, f_xr, n);
    agg_ep<128, true><<<agg_blocks, 256>>>(f_xl, f_xr, f_h, n);

    // Layer 1
    gemm_fused<128><<<gg, 256>>>(f_h, Wl1, Wr1, b1, f_xl, f_xr, n);
    agg_ep<128, true><<<agg_blocks, 256>>>(f_xl, f_xr, f_h2, n);

    // Layer 2 (DOUT=64, no relu) -> d_out
    gemm_fused<64><<<gg, 256>>>(f_h2, Wl2, Wr2, b2, f_xl, f_xr, n);
    agg_ep<64, false><<<agg_blocks, 256>>>(f_xl, f_xr, (float*)d_out, n);
}

// round 2
// speedup vs baseline: 1.5034x; 1.5034x over previous
#include <cuda_runtime.h>
#include <cstdint>
#include <cstddef>

// Problem constants (match reference)
#define NMAX 100000
#define EMAX 1600000
#define K_DIM 128

// ---- Scratch (device globals; no allocations allowed) ----
__device__ int   g_deg[NMAX];
__device__ int   g_rowptr[NMAX + 1];
__device__ int   g_fill[NMAX];
__device__ int   g_col[EMAX];
__device__ float g_xl[(size_t)NMAX * 128];   // aggregated-path transform
__device__ float g_xr[(size_t)NMAX * 128];   // self-path transform (+bias)
__device__ float g_h[(size_t)NMAX * 128];    // layer-0 output
__device__ float g_h2[(size_t)NMAX * 128];   // layer-1 output

// ============================================================
// CSR build (counting sort by dst), rebuilt every launch
// ============================================================
__global__ void zero_deg_k(int n) {
    int i = blockIdx.x * blockDim.x + threadIdx.x;
    if (i < n) g_deg[i] = 0;
}

__global__ void hist_k(const int* __restrict__ dst, int e) {
    int i = blockIdx.x * blockDim.x + threadIdx.x;
    if (i < e) atomicAdd(&g_deg[dst[i]], 1);
}

__global__ __launch_bounds__(1024) void scan_k(int n) {
    __shared__ int part[1024];
    int tid = threadIdx.x;
    int chunk = (n + 1023) >> 10;
    int beg = tid * chunk;
    int end = min(beg + chunk, n);
    int s = 0;
    for (int i = beg; i < end; i++) s += g_deg[i];
    part[tid] = s;
    __syncthreads();
    for (int off = 1; off < 1024; off <<= 1) {
        int v = (tid >= off) ? part[tid - off] : 0;
        __syncthreads();
        part[tid] += v;
        __syncthreads();
    }
    int base = part[tid] - s;  // exclusive prefix
    for (int i = beg; i < end; i++) {
        g_rowptr[i] = base;
        g_fill[i]   = base;
        base += g_deg[i];
    }
    if (tid == 1023) g_rowptr[n] = part[1023];
}

__global__ void scatter_k(const int* __restrict__ src, const int* __restrict__ dst, int e) {
    int i = blockIdx.x * blockDim.x + threadIdx.x;
    if (i < e) {
        int p = atomicAdd(&g_fill[dst[i]], 1);
        g_col[p] = src[i];
    }
}

// ============================================================
// tf32 rounding helper: fp32 -> tf32 bit pattern (round-to-nearest)
// ============================================================
__device__ __forceinline__ uint32_t f2tf(float x) {
    uint32_t u;
    asm("cvt.rna.tf32.f32 %0, %1;" : "=r"(u) : "f"(x));
    return u;
}

__device__ __forceinline__ void mma_tf32(
    float c[4], uint32_t a0, uint32_t a1, uint32_t a2, uint32_t a3,
    uint32_t b0, uint32_t b1)
{
    asm volatile(
        "mma.sync.aligned.m16n8k8.row.col.f32.tf32.tf32.f32 "
        "{%0,%1,%2,%3}, {%4,%5,%6,%7}, {%8,%9}, {%0,%1,%2,%3};"
        : "+f"(c[0]), "+f"(c[1]), "+f"(c[2]), "+f"(c[3])
        : "r"(a0), "r"(a1), "r"(a2), "r"(a3), "r"(b0), "r"(b1));
}

// ============================================================
// Fused dual GEMM (tf32 tensor cores):
//   Cl = A @ Wl ; Cr = A @ Wr + bias   (blockIdx.y selects)
// A: [n,128] row-major, W: [128,DOUT] row-major.
// Tile: BM=128 rows x DOUT cols, BK=16. 8 warps, one m16 row-group each.
// ============================================================
template <int DOUT>
__global__ __launch_bounds__(256) void gemm_mma(
    const float* __restrict__ A,
    const float* __restrict__ Wl, const float* __restrict__ Wr,
    const float* __restrict__ bias,
    float* __restrict__ Cl, float* __restrict__ Cr, int n)
{
    constexpr int BM = 128, BK = 16;
    constexpr int NF = DOUT / 8;            // n-fragments per warp

    __shared__ uint32_t As[BM][BK + 4];     // stride 20: conflict-free A-frag reads
    __shared__ uint32_t Bs[BK][DOUT + 4];   // stride DOUT+4: <=2-way B-frag reads

    const float* W = blockIdx.y ? Wr : Wl;
    float*       C = blockIdx.y ? Cr : Cl;
    const bool use_bias = (blockIdx.y == 1);

    const int tid  = threadIdx.x;
    const int warp = tid >> 5;
    const int lane = tid & 31;
    const int g    = lane >> 2;    // group (row within octet)
    const int tig  = lane & 3;     // thread in group
    const int row0 = blockIdx.x * BM;
    const int wrow = warp * 16;

    float acc[NF][4];
#pragma unroll
    for (int f = 0; f < NF; f++)
#pragma unroll
        for (int j = 0; j < 4; j++) acc[f][j] = 0.f;

    for (int k0 = 0; k0 < K_DIM; k0 += BK) {
        // ---- stage A tile: BM x BK, tf32-rounded ----
#pragma unroll
        for (int v = 0; v < (BM * BK) / (4 * 256); v++) {
            int idx = tid + v * 256;          // 0..511
            int r   = idx >> 2;
            int kq  = (idx & 3) * 4;
            float4 av = make_float4(0.f, 0.f, 0.f, 0.f);
            int gr = row0 + r;
            if (gr < n) av = *(const float4*)(A + (size_t)gr * K_DIM + k0 + kq);
            uint4 uv;
            uv.x = f2tf(av.x); uv.y = f2tf(av.y);
            uv.z = f2tf(av.z); uv.w = f2tf(av.w);
            *(uint4*)&As[r][kq] = uv;
        }
        // ---- stage B tile: BK x DOUT, tf32-rounded ----
#pragma unroll
        for (int v = 0; v < (BK * DOUT) / (4 * 256); v++) {
            int idx = tid + v * 256;
            int kk  = idx / (DOUT / 4);
            int c4  = (idx % (DOUT / 4)) * 4;
            float4 bv = *(const float4*)(W + (size_t)(k0 + kk) * DOUT + c4);
            uint4 uv;
            uv.x = f2tf(bv.x); uv.y = f2tf(bv.y);
            uv.z = f2tf(bv.z); uv.w = f2tf(bv.w);
            *(uint4*)&Bs[kk][c4] = uv;
        }
        __syncthreads();

#pragma unroll
        for (int ks = 0; ks < 2; ks++) {
            const int kb = ks * 8;
            uint32_t a0 = As[wrow + g][kb + tig];
            uint32_t a1 = As[wrow + g + 8][kb + tig];
            uint32_t a2 = As[wrow + g][kb + tig + 4];
            uint32_t a3 = As[wrow + g + 8][kb + tig + 4];
#pragma unroll
            for (int f = 0; f < NF; f++) {
                uint32_t b0 = Bs[kb + tig][f * 8 + g];
                uint32_t b1 = Bs[kb + tig + 4][f * 8 + g];
                mma_tf32(acc[f], a0, a1, a2, a3, b0, b1);
            }
        }
        __syncthreads();
    }

    // ---- epilogue ----
    const int r_lo = row0 + wrow + g;
    const int r_hi = r_lo + 8;
#pragma unroll
    for (int f = 0; f < NF; f++) {
        int col = f * 8 + 2 * tig;
        float bv0 = use_bias ? bias[col]     : 0.f;
        float bv1 = use_bias ? bias[col + 1] : 0.f;
        if (r_lo < n) {
            float2 o = make_float2(acc[f][0] + bv0, acc[f][1] + bv1);
            *(float2*)(C + (size_t)r_lo * DOUT + col) = o;
        }
        if (r_hi < n) {
            float2 o = make_float2(acc[f][2] + bv0, acc[f][3] + bv1);
            *(float2*)(C + (size_t)r_hi * DOUT + col) = o;
        }
    }
}

// ============================================================
// Aggregation + epilogue: out[n] = relu?( mean_{s in N(n)} xl[s] + xr[n] )
// One warp per destination node; register accumulation (no atomics).
// ============================================================
template <int DOUT, bool RELU>
__global__ __launch_bounds__(256) void agg_ep(
    const float* __restrict__ xl, const float* __restrict__ xr,
    float* __restrict__ out, int n)
{
    int gw   = (blockIdx.x * blockDim.x + threadIdx.x) >> 5;
    int lane = threadIdx.x & 31;
    if (gw >= n) return;

    int beg = g_rowptr[gw];
    int end = g_rowptr[gw + 1];
    float inv = 1.f / fmaxf((float)(end - beg), 1.f);

    if (DOUT == 128) {
        const float4* X = (const float4*)xl;
        float4 a0 = {0,0,0,0}, a1 = {0,0,0,0}, a2 = {0,0,0,0}, a3 = {0,0,0,0};
        int e = beg;
        for (; e + 3 < end; e += 4) {
            int s0 = g_col[e], s1 = g_col[e + 1], s2 = g_col[e + 2], s3 = g_col[e + 3];
            float4 v0 = X[s0 * 32 + lane];
            float4 v1 = X[s1 * 32 + lane];
            float4 v2 = X[s2 * 32 + lane];
            float4 v3 = X[s3 * 32 + lane];
            a0.x += v0.x; a0.y += v0.y; a0.z += v0.z; a0.w += v0.w;
            a1.x += v1.x; a1.y += v1.y; a1.z += v1.z; a1.w += v1.w;
            a2.x += v2.x; a2.y += v2.y; a2.z += v2.z; a2.w += v2.w;
            a3.x += v3.x; a3.y += v3.y; a3.z += v3.z; a3.w += v3.w;
        }
        for (; e < end; e++) {
            int s = g_col[e];
            float4 v = X[s * 32 + lane];
            a0.x += v.x; a0.y += v.y; a0.z += v.z; a0.w += v.w;
        }
        float4 r = ((const float4*)xr)[gw * 32 + lane];
        float4 o;
        o.x = (a0.x + a1.x + a2.x + a3.x) * inv + r.x;
        o.y = (a0.y + a1.y + a2.y + a3.y) * inv + r.y;
        o.z = (a0.z + a1.z + a2.z + a3.z) * inv + r.z;
        o.w = (a0.w + a1.w + a2.w + a3.w) * inv + r.w;
        if (RELU) {
            o.x = fmaxf(o.x, 0.f); o.y = fmaxf(o.y, 0.f);
            o.z = fmaxf(o.z, 0.f); o.w = fmaxf(o.w, 0.f);
        }
        ((float4*)out)[gw * 32 + lane] = o;
    } else {  // DOUT == 64
        const float2* X = (const float2*)xl;
        float2 a0 = {0,0}, a1 = {0,0}, a2 = {0,0}, a3 = {0,0};
        int e = beg;
        for (; e + 3 < end; e += 4) {
            int s0 = g_col[e], s1 = g_col[e + 1], s2 = g_col[e + 2], s3 = g_col[e + 3];
            float2 v0 = X[s0 * 32 + lane];
            float2 v1 = X[s1 * 32 + lane];
            float2 v2 = X[s2 * 32 + lane];
            float2 v3 = X[s3 * 32 + lane];
            a0.x += v0.x; a0.y += v0.y;
            a1.x += v1.x; a1.y += v1.y;
            a2.x += v2.x; a2.y += v2.y;
            a3.x += v3.x; a3.y += v3.y;
        }
        for (; e < end; e++) {
            int s = g_col[e];
            float2 v = X[s * 32 + lane];
            a0.x += v.x; a0.y += v.y;
        }
        float2 r = ((const float2*)xr)[gw * 32 + lane];
        float2 o;
        o.x = (a0.x + a1.x + a2.x + a3.x) * inv + r.x;
        o.y = (a0.y + a1.y + a2.y + a3.y) * inv + r.y;
        if (RELU) { o.x = fmaxf(o.x, 0.f); o.y = fmaxf(o.y, 0.f); }
        ((float2*)out)[gw * 32 + lane] = o;
    }
}

// ============================================================
// Launch
// ============================================================
extern "C" void kernel_launch(void* const* d_in, const int* in_sizes, int n_in,
                              void* d_out, int out_size)
{
    const float* x   = (const float*)d_in[0];
    const int*   ei  = (const int*)d_in[1];
    const float* Wl0 = (const float*)d_in[2];
    const float* Wr0 = (const float*)d_in[3];
    const float* b0  = (const float*)d_in[4];
    const float* Wl1 = (const float*)d_in[5];
    const float* Wr1 = (const float*)d_in[6];
    const float* b1  = (const float*)d_in[7];
    const float* Wl2 = (const float*)d_in[8];
    const float* Wr2 = (const float*)d_in[9];
    const float* b2  = (const float*)d_in[10];

    const int n = in_sizes[0] / 128;
    const int e = in_sizes[1] / 2;
    const int* src = ei;
    const int* dst = ei + e;

    void *pxl, *pxr, *ph, *ph2;
    cudaGetSymbolAddress(&pxl, g_xl);
    cudaGetSymbolAddress(&pxr, g_xr);
    cudaGetSymbolAddress(&ph,  g_h);
    cudaGetSymbolAddress(&ph2, g_h2);
    float* f_xl = (float*)pxl;
    float* f_xr = (float*)pxr;
    float* f_h  = (float*)ph;
    float* f_h2 = (float*)ph2;

    // CSR build (per-launch; deterministic up to int atomics ordering)
    zero_deg_k<<<(n + 255) / 256, 256>>>(n);
    hist_k<<<(e + 255) / 256, 256>>>(dst, e);
    scan_k<<<1, 1024>>>(n);
    scatter_k<<<(e + 255) / 256, 256>>>(src, dst, e);

    dim3 gg((n + 127) / 128, 2);
    int agg_blocks = (n + 7) / 8;  // 8 warps/block, one warp per node

    // Layer 0: h = relu(mean_agg(x@Wl0) + x@Wr0 + b0)
    gemm_mma<128><<<gg, 256>>>(x, Wl0, Wr0, b0, f_xl, f_xr, n);
    agg_ep<128, true><<<agg_blocks, 256>>>(f_xl, f_xr, f_h, n);

    // Layer 1
    gemm_mma<128><<<gg, 256>>>(f_h, Wl1, Wr1, b1, f_xl, f_xr, n);
    agg_ep<128, true><<<agg_blocks, 256>>>(f_xl, f_xr, f_h2, n);

    // Layer 2 (DOUT=64, no relu) -> d_out
    gemm_mma<64><<<gg, 256>>>(f_h2, Wl2, Wr2, b2, f_xl, f_xr, n);
    agg_ep<64, false><<<agg_blocks, 256>>>(f_xl, f_xr, (float*)d_out, n);
}